// round 4
// baseline (speedup 1.0000x reference)
#include <cuda_runtime.h>
#include <cstddef>
#include <math.h>

// Problem constants
#define BATCH 128
#define SEQL  20
#define EDIM  256
#define HDIM  512
#define NPOS  196      // 14*14
#define CDIM  2048
#define NCLS  2000
#define XDIM  768      // E + H
#define GDIM  1536     // 3*H

// ---------------- scratch (static device globals; no allocation) ----------------
__device__ float d_IH[(size_t)BATCH * HDIM * NPOS];   // img_hidden, layout [b][h][n]
__device__ float d_poolp[BATCH * 8 * NPOS];           // partial channel-max
__device__ float d_hbuf[BATCH * HDIM];                // hidden state
__device__ float d_xh[BATCH * XDIM];                  // GRU input x = concat(w, ctx) * v
__device__ float d_gi[BATCH * GDIM];                  // x @ Wih^T + bih
__device__ float d_gh[BATCH * GDIM];                  // h @ Whh^T + bhh
__device__ float d_fc1[BATCH * 1024];

// ---------------- helpers ----------------
// Packed fp32 FMA: d = a*b + d on both halves. On sm_100+ this maps to the
// dual-rate FFMA2 pipe; elsewhere fall back to two scalar fmaf (bit-identical
// per element, just half rate).
__device__ __forceinline__ void fma2(unsigned long long &d, unsigned long long a,
                                     unsigned long long b) {
#if defined(__CUDA_ARCH__) && (__CUDA_ARCH__ >= 1000)
    asm("fma.rn.f32x2 %0, %1, %2, %0;" : "+l"(d) : "l"(a), "l"(b));
#else
    float dx = __uint_as_float((unsigned int)(d & 0xffffffffull));
    float dy = __uint_as_float((unsigned int)(d >> 32));
    float ax = __uint_as_float((unsigned int)(a & 0xffffffffull));
    float ay = __uint_as_float((unsigned int)(a >> 32));
    float bx = __uint_as_float((unsigned int)(b & 0xffffffffull));
    float by = __uint_as_float((unsigned int)(b >> 32));
    dx = fmaf(ax, bx, dx);
    dy = fmaf(ay, by, dy);
    d = ((unsigned long long)__float_as_uint(dy) << 32) | __float_as_uint(dx);
#endif
}
__device__ __forceinline__ float2 ull2f2(unsigned long long u) {
    float2 f;
    f.x = __uint_as_float((unsigned int)(u & 0xffffffffull));
    f.y = __uint_as_float((unsigned int)(u >> 32));
    return f;
}

// ---------------- kernel 1: channel max-pool (partials over c) ----------------
// image layout [B][2048][196]; max over c for each (b,n). grid (128, 8), block 256.
__global__ void pool_kernel(const float *__restrict__ image) {
    int b = blockIdx.x, part = blockIdx.y;
    int n = threadIdx.x;
    if (n >= NPOS) return;
    const float *p = image + ((size_t)b * CDIM + (size_t)part * 256) * NPOS + n;
    float m = -3.4e38f;
#pragma unroll 8
    for (int c = 0; c < 256; c++) m = fmaxf(m, p[(size_t)c * NPOS]);
    d_poolp[((size_t)b * 8 + part) * NPOS + n] = m;
}

// ---------------- kernel 2: h0 = pooled @ W0^T + b0 ----------------
// grid 128, block 512
__global__ void h0_kernel(const float *__restrict__ W0, const float *__restrict__ b0) {
    __shared__ float sp[NPOS];
    int b = blockIdx.x, t = threadIdx.x;
    if (t < NPOS) {
        float m = -3.4e38f;
#pragma unroll
        for (int q = 0; q < 8; q++) m = fmaxf(m, d_poolp[((size_t)b * 8 + q) * NPOS + t]);
        sp[t] = m;
    }
    __syncthreads();
    float acc = b0[t];
    const float *wr = W0 + (size_t)t * NPOS;
#pragma unroll 4
    for (int n = 0; n < NPOS; n++) acc = fmaf(sp[n], wr[n], acc);
    d_hbuf[(size_t)b * HDIM + t] = acc;
}

// ---------------- kernel 3: img_hidden GEMM ----------------
// IH[b][h][n] = sum_c W[h][c] * image[b][c][n] + bias[h]
// grid (4 ntiles, 8 htiles, 128 b), block 256. BM=BN=64, BK=16, micro 4x4 via f32x2.
// A (weights) stored PRE-DUPLICATED in smem as float2(w,w) so the inner loop is
// pure LDS.128 + FFMA2 (no pack/PRMT instructions).
__global__ void img_gemm_kernel(const float *__restrict__ image,
                                const float *__restrict__ W,
                                const float *__restrict__ bias) {
    __shared__ __align__(16) float2 Asd[16][64];  // dup'd W values, [k][h]
    __shared__ __align__(16) float  Bs[16][64];   // image tile, [k][n]
    const int t = threadIdx.x;
    const int n0 = blockIdx.x * 64, h0 = blockIdx.y * 64, b = blockIdx.z;
    const int tx = t & 15, ty = t >> 4;
    unsigned long long acc[4][2];
#pragma unroll
    for (int r = 0; r < 4; r++) { acc[r][0] = 0ull; acc[r][1] = 0ull; }

    const float *imgB = image + (size_t)b * CDIM * NPOS;
    const int ar = t >> 2, ac = (t & 3) * 4;      // A loader: 64 rows x 4 float4
    const int br = t >> 4, bj = (t & 15) * 4;     // B loader: 16 rows x 16 float4

    for (int k0 = 0; k0 < CDIM; k0 += 16) {
        float4 a4 = *(const float4 *)(W + (size_t)(h0 + ar) * CDIM + k0 + ac);
        Asd[ac + 0][ar] = make_float2(a4.x, a4.x);
        Asd[ac + 1][ar] = make_float2(a4.y, a4.y);
        Asd[ac + 2][ar] = make_float2(a4.z, a4.z);
        Asd[ac + 3][ar] = make_float2(a4.w, a4.w);
        int col = n0 + bj;
        float4 b4 = make_float4(0.f, 0.f, 0.f, 0.f);
        if (col + 3 < NPOS)  // col multiple of 4; 196%4==0 -> vector either fully valid or fully OOB
            b4 = *(const float4 *)(imgB + (size_t)(k0 + br) * NPOS + col);
        *(float4 *)&Bs[br][bj] = b4;
        __syncthreads();
#pragma unroll
        for (int kk = 0; kk < 16; kk++) {
            ulonglong2 a01 = *(const ulonglong2 *)&Asd[kk][ty * 4];
            ulonglong2 a23 = *(const ulonglong2 *)&Asd[kk][ty * 4 + 2];
            ulonglong2 bv  = *(const ulonglong2 *)&Bs[kk][tx * 4];
            fma2(acc[0][0], a01.x, bv.x); fma2(acc[0][1], a01.x, bv.y);
            fma2(acc[1][0], a01.y, bv.x); fma2(acc[1][1], a01.y, bv.y);
            fma2(acc[2][0], a23.x, bv.x); fma2(acc[2][1], a23.x, bv.y);
            fma2(acc[3][0], a23.y, bv.x); fma2(acc[3][1], a23.y, bv.y);
        }
        __syncthreads();
    }
#pragma unroll
    for (int r = 0; r < 4; r++) {
        int h = h0 + ty * 4 + r;
        float bb = bias[h];
        float *dst = d_IH + ((size_t)b * HDIM + h) * NPOS;
#pragma unroll
        for (int p = 0; p < 2; p++) {
            float2 v2 = ull2f2(acc[r][p]);
            int n = n0 + tx * 4 + p * 2;
            if (n < NPOS)     dst[n]     = v2.x + bb;
            if (n + 1 < NPOS) dst[n + 1] = v2.y + bb;
        }
    }
}

// ---------------- generic NT GEMM: C[m][n] = sum_k A[m][k]*W[n][k] + bias[n] ----------------
// BM=64, BN=32, BK=16, block 256, micro 2x2 (f32x2 on n-pairs). M covered exactly by grid.y.
// Requires: K % 16 == 0, lda/ldc legal, A has M>=m0+64 rows.
__device__ __forceinline__ void gemm_nt_dev(const float *__restrict__ A, int lda,
                                            const float *__restrict__ W,
                                            const float *__restrict__ bias,
                                            int N, int K,
                                            float *__restrict__ C, int ldc, bool relu) {
    __shared__ __align__(16) float2 Asd[16][64];  // dup'd A, [k][m]
    __shared__ __align__(16) float  Bs[16][32];   // W tile transposed, [k][n]
    const int t = threadIdx.x;
    const int m0 = blockIdx.y * 64, j0 = blockIdx.x * 32;
    const int tx = t & 7, ty = t >> 3;
    unsigned long long acc[2][2] = {0ull, 0ull, 0ull, 0ull};
    const int ar = t >> 2, ac = (t & 3) * 4;

    for (int k0 = 0; k0 < K; k0 += 16) {
        float4 a4 = *(const float4 *)(A + (size_t)(m0 + ar) * lda + k0 + ac);
        Asd[ac + 0][ar] = make_float2(a4.x, a4.x);
        Asd[ac + 1][ar] = make_float2(a4.y, a4.y);
        Asd[ac + 2][ar] = make_float2(a4.z, a4.z);
        Asd[ac + 3][ar] = make_float2(a4.w, a4.w);
        if (t < 128) {
            int r = t >> 2, cc = (t & 3) * 4;
            float4 b4 = make_float4(0.f, 0.f, 0.f, 0.f);
            if (j0 + r < N) b4 = *(const float4 *)(W + (size_t)(j0 + r) * K + k0 + cc);
            Bs[cc + 0][r] = b4.x; Bs[cc + 1][r] = b4.y;
            Bs[cc + 2][r] = b4.z; Bs[cc + 3][r] = b4.w;
        }
        __syncthreads();
#pragma unroll
        for (int kk = 0; kk < 16; kk++) {
            ulonglong2 av = *(const ulonglong2 *)&Asd[kk][ty * 2];
            ulonglong2 bv = *(const ulonglong2 *)&Bs[kk][tx * 4];
            fma2(acc[0][0], av.x, bv.x); fma2(acc[0][1], av.x, bv.y);
            fma2(acc[1][0], av.y, bv.x); fma2(acc[1][1], av.y, bv.y);
        }
        __syncthreads();
    }
#pragma unroll
    for (int r = 0; r < 2; r++) {
        int m = m0 + ty * 2 + r;
#pragma unroll
        for (int p = 0; p < 2; p++) {
            float2 v2 = ull2f2(acc[r][p]);
            int n = j0 + tx * 4 + p * 2;
            if (n < N) {
                float o = v2.x + bias[n];
                if (relu) o = fmaxf(o, 0.f);
                C[(size_t)m * ldc + n] = o;
            }
            if (n + 1 < N) {
                float o = v2.y + bias[n + 1];
                if (relu) o = fmaxf(o, 0.f);
                C[(size_t)m * ldc + n + 1] = o;
            }
        }
    }
}

// Fused GRU GEMM: z==0 -> GI = x@Wih^T + bih ; z==1 -> GH = h@Whh^T + bhh
// grid (48, 2, 2), block 256
__global__ void gru_gemm_kernel(const float *__restrict__ Wih, const float *__restrict__ Whh,
                                const float *__restrict__ bih, const float *__restrict__ bhh) {
    if (blockIdx.z == 0)
        gemm_nt_dev(d_xh, XDIM, Wih, bih, GDIM, XDIM, d_gi, GDIM, false);
    else
        gemm_nt_dev(d_hbuf, HDIM, Whh, bhh, GDIM, HDIM, d_gh, GDIM, false);
}

__global__ void fc1_kernel(const float *__restrict__ W, const float *__restrict__ b) {
    gemm_nt_dev(d_hbuf, HDIM, W, b, 1024, HDIM, d_fc1, 1024, true);
}
__global__ void fc2_kernel(const float *__restrict__ W, const float *__restrict__ b,
                           float *__restrict__ out) {
    gemm_nt_dev(d_fc1, 1024, W, b, NCLS, 1024, out, NCLS, false);
}

// ---------------- gate math (shared by step & final) ----------------
__device__ __forceinline__ float gru_update(int b, int j, float hp) {
    const float *gi = d_gi + (size_t)b * GDIM;
    const float *gh = d_gh + (size_t)b * GDIM;
    float r = 1.f / (1.f + expf(-(gi[j] + gh[j])));
    float z = 1.f / (1.f + expf(-(gi[HDIM + j] + gh[HDIM + j])));
    float n = tanhf(gi[2 * HDIM + j] + r * gh[2 * HDIM + j]);
    return (1.f - z) * n + z * hp;
}

// ---------------- per-step kernel: [gates of prev step] + attention + x ----------------
// grid 128 (b), block 256
__global__ void step_kernel(const int *__restrict__ question,
                            const float *__restrict__ emb,
                            const float *__restrict__ v, int t, int first) {
    __shared__ float sh_h[HDIM];
    __shared__ float sh_e[NPOS];
    __shared__ float sh_red[8];
    __shared__ float sh_scalar[2];
    const int b = blockIdx.x, tid = threadIdx.x;

    // phase 0: finalize h from previous step's GI/GH (elementwise, in-place safe)
    if (first) {
#pragma unroll
        for (int q = 0; q < 2; q++) {
            int j = tid + q * 256;
            sh_h[j] = d_hbuf[(size_t)b * HDIM + j];
        }
    } else {
#pragma unroll
        for (int q = 0; q < 2; q++) {
            int j = tid + q * 256;
            float hp = d_hbuf[(size_t)b * HDIM + j];
            float hn = gru_update(b, j, hp);
            sh_h[j] = hn;
            d_hbuf[(size_t)b * HDIM + j] = hn;
        }
    }
    __syncthreads();

    // phase 1: energy[n] = sum_h h[h] * IH[b][h][n]  (coalesced over tid=n)
    float e = -3.4e38f;
    if (tid < NPOS) {
        const float *col = d_IH + (size_t)b * HDIM * NPOS + tid;
        float acc = 0.f;
#pragma unroll 8
        for (int h = 0; h < HDIM; h++) acc = fmaf(sh_h[h], col[(size_t)h * NPOS], acc);
        e = acc;
    }
    // block max
    float m = e;
#pragma unroll
    for (int o = 16; o > 0; o >>= 1) m = fmaxf(m, __shfl_xor_sync(0xffffffffu, m, o));
    if ((tid & 31) == 0) sh_red[tid >> 5] = m;
    __syncthreads();
    if (tid == 0) {
        float mm = sh_red[0];
#pragma unroll
        for (int i = 1; i < 8; i++) mm = fmaxf(mm, sh_red[i]);
        sh_scalar[0] = mm;
    }
    __syncthreads();
    float mx = sh_scalar[0];
    float ex = (tid < NPOS) ? expf(e - mx) : 0.f;
    if (tid < NPOS) sh_e[tid] = ex;
    float s = ex;
#pragma unroll
    for (int o = 16; o > 0; o >>= 1) s += __shfl_xor_sync(0xffffffffu, s, o);
    if ((tid & 31) == 0) sh_red[tid >> 5] = s;
    __syncthreads();
    if (tid == 0) {
        float ss = 0.f;
#pragma unroll
        for (int i = 0; i < 8; i++) ss += sh_red[i];
        sh_scalar[1] = 1.f / ss;
    }
    __syncthreads();
    float inv = sh_scalar[1];

    // phase 2: context[h] = (sum_n ex[n]*IH[b][h][n]) * inv ; x[256+h] = ctx*v[256+h]
    int wid = tid >> 5, lane = tid & 31;
    for (int h = wid; h < HDIM; h += 8) {
        const float *row = d_IH + ((size_t)b * HDIM + h) * NPOS;
        float acc = 0.f;
#pragma unroll
        for (int nb = 0; nb < 224; nb += 32) {
            int n = nb + lane;
            if (n < NPOS) acc = fmaf(sh_e[n], row[n], acc);
        }
#pragma unroll
        for (int o = 16; o > 0; o >>= 1) acc += __shfl_xor_sync(0xffffffffu, acc, o);
        if (lane == 0)
            d_xh[(size_t)b * XDIM + EDIM + h] = acc * inv * v[EDIM + h];
    }

    // phase 3: word part: x[k] = emb[question[b][t]][k] * v[k], k = 0..255
    int w = question[b * SEQL + t];
    d_xh[(size_t)b * XDIM + tid] = emb[(size_t)w * EDIM + tid] * v[tid];
}

// ---------------- final gate update after last GEMM ----------------
__global__ void final_gates_kernel() {
    int b = blockIdx.x, j = threadIdx.x;
    float hp = d_hbuf[(size_t)b * HDIM + j];
    d_hbuf[(size_t)b * HDIM + j] = gru_update(b, j, hp);
}

// ---------------- launch ----------------
extern "C" void kernel_launch(void *const *d_in, const int *in_sizes, int n_in,
                              void *d_out, int out_size) {
    const int   *question = (const int *)d_in[0];
    const float *image    = (const float *)d_in[1];
    const float *emb      = (const float *)d_in[2];
    const float *v        = (const float *)d_in[3];
    const float *Wih      = (const float *)d_in[4];
    const float *Whh      = (const float *)d_in[5];
    const float *bih      = (const float *)d_in[6];
    const float *bhh      = (const float *)d_in[7];
    const float *Wimg2h   = (const float *)d_in[8];
    const float *bimg2h   = (const float *)d_in[9];
    const float *Wimg2h0  = (const float *)d_in[10];
    const float *bimg2h0  = (const float *)d_in[11];
    const float *Wfc1     = (const float *)d_in[12];
    const float *bfc1     = (const float *)d_in[13];
    const float *Wfc2     = (const float *)d_in[14];
    const float *bfc2     = (const float *)d_in[15];
    float *out = (float *)d_out;

    pool_kernel<<<dim3(BATCH, 8), 256>>>(image);
    h0_kernel<<<BATCH, HDIM>>>(Wimg2h0, bimg2h0);
    img_gemm_kernel<<<dim3(4, 8, BATCH), 256>>>(image, Wimg2h, bimg2h);

    for (int t = 0; t < SEQL; t++) {
        step_kernel<<<BATCH, 256>>>(question, emb, v, t, t == 0 ? 1 : 0);
        gru_gemm_kernel<<<dim3(48, 2, 2), 256>>>(Wih, Whh, bih, bhh);
    }
    final_gates_kernel<<<BATCH, HDIM>>>();

    fc1_kernel<<<dim3(32, 2), 256>>>(Wfc1, bfc1);
    fc2_kernel<<<dim3(63, 2), 256>>>(Wfc2, bfc2, out);
}

// round 6
// speedup vs baseline: 1.4793x; 1.4793x over previous
#include <cuda_runtime.h>
#include <cstddef>
#include <math.h>

// Problem constants
#define BATCH 128
#define SEQL  20
#define EDIM  256
#define HDIM  512
#define NPOS  196      // 14*14
#define CDIM  2048
#define NCLS  2000
#define XDIM  768      // E + H
#define GDIM  1536     // 3*H

// ---------------- scratch (static device globals; no allocation) ----------------
__device__ float d_IH[(size_t)BATCH * HDIM * NPOS];   // img_hidden, layout [b][h][n]
__device__ float d_poolp[BATCH * 8 * NPOS];           // partial channel-max
__device__ float d_hbuf[BATCH * HDIM];                // hidden state
__device__ float d_xc[BATCH * HDIM];                  // ctx * v_ctx (GRU input, ctx part)
__device__ float d_xw[BATCH * SEQL * EDIM];           // word*v for all steps
__device__ float d_giW[(size_t)BATCH * SEQL * GDIM];  // word part of GI (+bih), all steps
__device__ float d_gic0[BATCH * GDIM];                // ctx part of GI, K-half 0
__device__ float d_gic1[BATCH * GDIM];                // ctx part of GI, K-half 1
__device__ float d_gh0[BATCH * GDIM];                 // h@Whh^T half 0 (+bhh)
__device__ float d_gh1[BATCH * GDIM];                 // h@Whh^T half 1
__device__ float d_fc1[BATCH * 1024];

// ---------------- helpers ----------------
// Packed fp32 FMA: d = a*b + d on both halves (FFMA2 on sm_100+).
__device__ __forceinline__ void fma2(unsigned long long &d, unsigned long long a,
                                     unsigned long long b) {
#if defined(__CUDA_ARCH__) && (__CUDA_ARCH__ >= 1000)
    asm("fma.rn.f32x2 %0, %1, %2, %0;" : "+l"(d) : "l"(a), "l"(b));
#else
    float dx = __uint_as_float((unsigned int)(d & 0xffffffffull));
    float dy = __uint_as_float((unsigned int)(d >> 32));
    float ax = __uint_as_float((unsigned int)(a & 0xffffffffull));
    float ay = __uint_as_float((unsigned int)(a >> 32));
    float bx = __uint_as_float((unsigned int)(b & 0xffffffffull));
    float by = __uint_as_float((unsigned int)(b >> 32));
    dx = fmaf(ax, bx, dx);
    dy = fmaf(ay, by, dy);
    d = ((unsigned long long)__float_as_uint(dy) << 32) | __float_as_uint(dx);
#endif
}
__device__ __forceinline__ float2 ull2f2(unsigned long long u) {
    float2 f;
    f.x = __uint_as_float((unsigned int)(u & 0xffffffffull));
    f.y = __uint_as_float((unsigned int)(u >> 32));
    return f;
}

// ---------------- kernel 1: channel max-pool (partials over c) ----------------
__global__ void pool_kernel(const float *__restrict__ image) {
    int b = blockIdx.x, part = blockIdx.y;
    int n = threadIdx.x;
    if (n >= NPOS) return;
    const float *p = image + ((size_t)b * CDIM + (size_t)part * 256) * NPOS + n;
    float m = -3.4e38f;
#pragma unroll 8
    for (int c = 0; c < 256; c++) m = fmaxf(m, p[(size_t)c * NPOS]);
    d_poolp[((size_t)b * 8 + part) * NPOS + n] = m;
}

// ---------------- kernel 2: h0 = pooled @ W0^T + b0 ----------------
__global__ void h0_kernel(const float *__restrict__ W0, const float *__restrict__ b0) {
    __shared__ float sp[NPOS];
    int b = blockIdx.x, t = threadIdx.x;
    if (t < NPOS) {
        float m = -3.4e38f;
#pragma unroll
        for (int q = 0; q < 8; q++) m = fmaxf(m, d_poolp[((size_t)b * 8 + q) * NPOS + t]);
        sp[t] = m;
    }
    __syncthreads();
    float acc = b0[t];
    const float *wr = W0 + (size_t)t * NPOS;
#pragma unroll 4
    for (int n = 0; n < NPOS; n++) acc = fmaf(sp[n], wr[n], acc);
    d_hbuf[(size_t)b * HDIM + t] = acc;
}

// ---------------- kernel: build word inputs for all steps ----------------
// xw[(b*SEQL+t)][k] = emb[question[b][t]][k] * v[k]
__global__ void build_xw_kernel(const int *__restrict__ question,
                                const float *__restrict__ emb,
                                const float *__restrict__ v) {
    int b = blockIdx.x, t = blockIdx.y, k = threadIdx.x;
    int w = question[b * SEQL + t];
    d_xw[((size_t)b * SEQL + t) * EDIM + k] = emb[(size_t)w * EDIM + k] * v[k];
}

// ---------------- kernel: img_hidden GEMM (tile 128h x 64n, micro 8x4) ----------------
// IH[b][h][n] = sum_c W[h][c] * image[b][c][n] + bias[h]
// grid (4 ntiles, 4 htiles, 128 b), block 256.
__global__ void __launch_bounds__(256)
img_gemm_kernel(const float *__restrict__ image,
                const float *__restrict__ W,
                const float *__restrict__ bias) {
    __shared__ __align__(16) float2 Asd[16][128];  // dup'd W values, [k][h]
    __shared__ __align__(16) float  Bs[16][64];    // image tile, [k][n]
    const int t = threadIdx.x;
    const int n0 = blockIdx.x * 64, h0 = blockIdx.y * 128, b = blockIdx.z;
    const int tx = t & 15, ty = t >> 4;            // tx: n (x4), ty: h (x8)
    unsigned long long acc[8][2];
#pragma unroll
    for (int r = 0; r < 8; r++) { acc[r][0] = 0ull; acc[r][1] = 0ull; }

    const float *imgB = image + (size_t)b * CDIM * NPOS;
    const int ar = t >> 1, ac = (t & 1) * 8;       // A: 128 rows x (2 x float4)
    const int br = t >> 4, bj = (t & 15) * 4;      // B: 16 rows x 16 float4

    for (int k0 = 0; k0 < CDIM; k0 += 16) {
        const float *wr = W + (size_t)(h0 + ar) * CDIM + k0 + ac;
        float4 a4 = *(const float4 *)(wr);
        float4 a5 = *(const float4 *)(wr + 4);
        Asd[ac + 0][ar] = make_float2(a4.x, a4.x);
        Asd[ac + 1][ar] = make_float2(a4.y, a4.y);
        Asd[ac + 2][ar] = make_float2(a4.z, a4.z);
        Asd[ac + 3][ar] = make_float2(a4.w, a4.w);
        Asd[ac + 4][ar] = make_float2(a5.x, a5.x);
        Asd[ac + 5][ar] = make_float2(a5.y, a5.y);
        Asd[ac + 6][ar] = make_float2(a5.z, a5.z);
        Asd[ac + 7][ar] = make_float2(a5.w, a5.w);
        int col = n0 + bj;
        float4 b4 = make_float4(0.f, 0.f, 0.f, 0.f);
        if (col + 3 < NPOS)
            b4 = *(const float4 *)(imgB + (size_t)(k0 + br) * NPOS + col);
        *(float4 *)&Bs[br][bj] = b4;
        __syncthreads();
#pragma unroll
        for (int kk = 0; kk < 16; kk++) {
            ulonglong2 a01 = *(const ulonglong2 *)&Asd[kk][ty * 8];
            ulonglong2 a23 = *(const ulonglong2 *)&Asd[kk][ty * 8 + 2];
            ulonglong2 a45 = *(const ulonglong2 *)&Asd[kk][ty * 8 + 4];
            ulonglong2 a67 = *(const ulonglong2 *)&Asd[kk][ty * 8 + 6];
            ulonglong2 bv  = *(const ulonglong2 *)&Bs[kk][tx * 4];
            fma2(acc[0][0], a01.x, bv.x); fma2(acc[0][1], a01.x, bv.y);
            fma2(acc[1][0], a01.y, bv.x); fma2(acc[1][1], a01.y, bv.y);
            fma2(acc[2][0], a23.x, bv.x); fma2(acc[2][1], a23.x, bv.y);
            fma2(acc[3][0], a23.y, bv.x); fma2(acc[3][1], a23.y, bv.y);
            fma2(acc[4][0], a45.x, bv.x); fma2(acc[4][1], a45.x, bv.y);
            fma2(acc[5][0], a45.y, bv.x); fma2(acc[5][1], a45.y, bv.y);
            fma2(acc[6][0], a67.x, bv.x); fma2(acc[6][1], a67.x, bv.y);
            fma2(acc[7][0], a67.y, bv.x); fma2(acc[7][1], a67.y, bv.y);
        }
        __syncthreads();
    }
#pragma unroll
    for (int r = 0; r < 8; r++) {
        int h = h0 + ty * 8 + r;
        float bb = bias[h];
        float *dst = d_IH + ((size_t)b * HDIM + h) * NPOS;
#pragma unroll
        for (int p = 0; p < 2; p++) {
            float2 v2 = ull2f2(acc[r][p]);
            int n = n0 + tx * 4 + p * 2;
            if (n < NPOS)     dst[n]     = v2.x + bb;
            if (n + 1 < NPOS) dst[n + 1] = v2.y + bb;
        }
    }
}

// ---------------- generic NT GEMM with K-offsets ----------------
// C[m][j] = sum_{k<Klen} A[m][koffA+k]*W[j][koffW+k] (+ bias[j]) ; BM=64, BN=32, BK=16.
// Requires Klen % 16 == 0, M covered exactly by grid.y*64.
__device__ __forceinline__ void gemm_nt_dev(const float *__restrict__ A, int lda, int koffA,
                                            const float *__restrict__ W, int ldw, int koffW,
                                            const float *__restrict__ bias,
                                            int N, int Klen,
                                            float *__restrict__ C, int ldc, bool relu) {
    __shared__ __align__(16) float2 Asd[16][64];
    __shared__ __align__(16) float  Bs[16][32];
    const int t = threadIdx.x;
    const int m0 = blockIdx.y * 64, j0 = blockIdx.x * 32;
    const int tx = t & 7, ty = t >> 3;
    unsigned long long acc[2][2] = {0ull, 0ull, 0ull, 0ull};
    const int ar = t >> 2, ac = (t & 3) * 4;

    for (int k0 = 0; k0 < Klen; k0 += 16) {
        float4 a4 = *(const float4 *)(A + (size_t)(m0 + ar) * lda + koffA + k0 + ac);
        Asd[ac + 0][ar] = make_float2(a4.x, a4.x);
        Asd[ac + 1][ar] = make_float2(a4.y, a4.y);
        Asd[ac + 2][ar] = make_float2(a4.z, a4.z);
        Asd[ac + 3][ar] = make_float2(a4.w, a4.w);
        if (t < 128) {
            int r = t >> 2, cc = (t & 3) * 4;
            float4 b4 = make_float4(0.f, 0.f, 0.f, 0.f);
            if (j0 + r < N) b4 = *(const float4 *)(W + (size_t)(j0 + r) * ldw + koffW + k0 + cc);
            Bs[cc + 0][r] = b4.x; Bs[cc + 1][r] = b4.y;
            Bs[cc + 2][r] = b4.z; Bs[cc + 3][r] = b4.w;
        }
        __syncthreads();
#pragma unroll
        for (int kk = 0; kk < 16; kk++) {
            ulonglong2 av = *(const ulonglong2 *)&Asd[kk][ty * 2];
            ulonglong2 bv = *(const ulonglong2 *)&Bs[kk][tx * 4];
            fma2(acc[0][0], av.x, bv.x); fma2(acc[0][1], av.x, bv.y);
            fma2(acc[1][0], av.y, bv.x); fma2(acc[1][1], av.y, bv.y);
        }
        __syncthreads();
    }
#pragma unroll
    for (int r = 0; r < 2; r++) {
        int m = m0 + ty * 2 + r;
#pragma unroll
        for (int p = 0; p < 2; p++) {
            float2 v2 = ull2f2(acc[r][p]);
            int n = j0 + tx * 4 + p * 2;
            if (n < N) {
                float o = v2.x + (bias ? bias[n] : 0.f);
                if (relu) o = fmaxf(o, 0.f);
                C[(size_t)m * ldc + n] = o;
            }
            if (n + 1 < N) {
                float o = v2.y + (bias ? bias[n + 1] : 0.f);
                if (relu) o = fmaxf(o, 0.f);
                C[(size_t)m * ldc + n + 1] = o;
            }
        }
    }
}

// giW = xw @ Wih[:, 0:256]^T + bih  over all (b,t): M=2560. grid (48, 40)
__global__ void __launch_bounds__(256)
giw_gemm_kernel(const float *__restrict__ Wih, const float *__restrict__ bih) {
    gemm_nt_dev(d_xw, EDIM, 0, Wih, XDIM, 0, bih, GDIM, EDIM, d_giW, GDIM, false);
}

// Per-step GRU GEMMs, split-K(=2). grid (48, 2, 4)
// z0: gic0 = xc @ Wih[:,256:512]^T         z1: gic1 = xc @ Wih[:,512:768]^T
// z2: gh0  = h  @ Whh[:,0:256]^T + bhh     z3: gh1  = h  @ Whh[:,256:512]^T
__global__ void __launch_bounds__(256)
gru_gemm_kernel(const float *__restrict__ Wih, const float *__restrict__ Whh,
                const float *__restrict__ bhh) {
    int z = blockIdx.z;
    if (z == 0)
        gemm_nt_dev(d_xc, HDIM, 0,   Wih, XDIM, EDIM,       0,   GDIM, 256, d_gic0, GDIM, false);
    else if (z == 1)
        gemm_nt_dev(d_xc, HDIM, 256, Wih, XDIM, EDIM + 256, 0,   GDIM, 256, d_gic1, GDIM, false);
    else if (z == 2)
        gemm_nt_dev(d_hbuf, HDIM, 0,   Whh, HDIM, 0,   bhh, GDIM, 256, d_gh0, GDIM, false);
    else
        gemm_nt_dev(d_hbuf, HDIM, 256, Whh, HDIM, 256, 0,   GDIM, 256, d_gh1, GDIM, false);
}

__global__ void __launch_bounds__(256)
fc1_kernel(const float *__restrict__ W, const float *__restrict__ b) {
    gemm_nt_dev(d_hbuf, HDIM, 0, W, HDIM, 0, b, 1024, HDIM, d_fc1, 1024, true);
}
__global__ void __launch_bounds__(256)
fc2_kernel(const float *__restrict__ W, const float *__restrict__ b,
           float *__restrict__ out) {
    gemm_nt_dev(d_fc1, 1024, 0, W, 1024, 0, b, NCLS, 1024, out, NCLS, false);
}

// ---------------- gate math ----------------
// gi = giW[b][tprev] + gic0 + gic1 (bih inside giW); gh = gh0 + gh1 (bhh inside gh0)
__device__ __forceinline__ float gru_update(int b, int tprev, int j, float hp) {
    size_t mw = ((size_t)b * SEQL + tprev) * GDIM;
    size_t mc = (size_t)b * GDIM;
    float gir = d_giW[mw + j]            + d_gic0[mc + j]            + d_gic1[mc + j];
    float giz = d_giW[mw + HDIM + j]     + d_gic0[mc + HDIM + j]     + d_gic1[mc + HDIM + j];
    float gin = d_giW[mw + 2 * HDIM + j] + d_gic0[mc + 2 * HDIM + j] + d_gic1[mc + 2 * HDIM + j];
    float ghr = d_gh0[mc + j]            + d_gh1[mc + j];
    float ghz = d_gh0[mc + HDIM + j]     + d_gh1[mc + HDIM + j];
    float ghn = d_gh0[mc + 2 * HDIM + j] + d_gh1[mc + 2 * HDIM + j];
    float r = 1.f / (1.f + expf(-(gir + ghr)));
    float z = 1.f / (1.f + expf(-(giz + ghz)));
    float n = tanhf(gin + r * ghn);
    return (1.f - z) * n + z * hp;
}

// ---------------- per-step fused kernel ----------------
// grid 128 (b), block 512.
// phase 0: finalize h (gates of prev step); phase 1: energy (2-way h split);
// softmax; phase 2: context -> d_xc.
__global__ void __launch_bounds__(512)
step_kernel(const float *__restrict__ v, int t) {
    __shared__ float sh_h[HDIM];
    __shared__ float sh_p[2 * NPOS];
    __shared__ float sh_e[NPOS];
    __shared__ float sh_red[8];
    __shared__ float sh_scalar[2];
    const int b = blockIdx.x, tid = threadIdx.x;

    // phase 0: gates
    {
        float hp = d_hbuf[(size_t)b * HDIM + tid];
        float hn = (t == 0) ? hp : gru_update(b, t - 1, tid, hp);
        sh_h[tid] = hn;
        if (t != 0) d_hbuf[(size_t)b * HDIM + tid] = hn;
    }
    __syncthreads();

    // phase 1: energy, h split in two halves of 256
    {
        int half = (tid >= 256) ? 1 : 0;
        int n = tid - half * 256;
        if (n < NPOS) {
            const float *col = d_IH + ((size_t)b * HDIM + half * 256) * NPOS + n;
            const float *hh = sh_h + half * 256;
            float a0 = 0.f, a1 = 0.f, a2 = 0.f, a3 = 0.f;
#pragma unroll 8
            for (int h = 0; h < 256; h += 4) {
                a0 = fmaf(hh[h + 0], col[(size_t)(h + 0) * NPOS], a0);
                a1 = fmaf(hh[h + 1], col[(size_t)(h + 1) * NPOS], a1);
                a2 = fmaf(hh[h + 2], col[(size_t)(h + 2) * NPOS], a2);
                a3 = fmaf(hh[h + 3], col[(size_t)(h + 3) * NPOS], a3);
            }
            sh_p[half * NPOS + n] = (a0 + a1) + (a2 + a3);
        }
    }
    __syncthreads();

    // softmax over 196 (threads 0..223 participate in reduce)
    float e = -3.4e38f;
    if (tid < NPOS) e = sh_p[tid] + sh_p[NPOS + tid];
    if (tid < 224) {
        float m = e;
#pragma unroll
        for (int o = 16; o > 0; o >>= 1) m = fmaxf(m, __shfl_xor_sync(0xffffffffu, m, o));
        if ((tid & 31) == 0) sh_red[tid >> 5] = m;
    }
    __syncthreads();
    if (tid == 0) {
        float mm = sh_red[0];
#pragma unroll
        for (int i = 1; i < 7; i++) mm = fmaxf(mm, sh_red[i]);
        sh_scalar[0] = mm;
    }
    __syncthreads();
    float mx = sh_scalar[0];
    float ex = (tid < NPOS) ? expf(e - mx) : 0.f;
    if (tid < NPOS) sh_e[tid] = ex;
    if (tid < 224) {
        float s = ex;
#pragma unroll
        for (int o = 16; o > 0; o >>= 1) s += __shfl_xor_sync(0xffffffffu, s, o);
        if ((tid & 31) == 0) sh_red[tid >> 5] = s;
    }
    __syncthreads();
    if (tid == 0) {
        float ss = 0.f;
#pragma unroll
        for (int i = 0; i < 7; i++) ss += sh_red[i];
        sh_scalar[1] = 1.f / ss;
    }
    __syncthreads();
    float inv = sh_scalar[1];

    // phase 2: context; 16 warps x 32 h-rows each (independent 7-load chains)
    {
        int w = tid >> 5, lane = tid & 31;
        int hbase = w * 32;
#pragma unroll 4
        for (int rr = 0; rr < 32; rr++) {
            int h = hbase + rr;
            const float *row = d_IH + ((size_t)b * HDIM + h) * NPOS;
            float acc = 0.f;
#pragma unroll
            for (int c = 0; c < 7; c++) {
                int n = c * 32 + lane;
                if (n < NPOS) acc = fmaf(sh_e[n], row[n], acc);
            }
#pragma unroll
            for (int o = 16; o > 0; o >>= 1) acc += __shfl_xor_sync(0xffffffffu, acc, o);
            if (lane == 0)
                d_xc[(size_t)b * HDIM + h] = acc * inv * v[EDIM + h];
        }
    }
}

// ---------------- final gate update after last GEMM ----------------
__global__ void __launch_bounds__(512) final_gates_kernel() {
    int b = blockIdx.x, j = threadIdx.x;
    float hp = d_hbuf[(size_t)b * HDIM + j];
    d_hbuf[(size_t)b * HDIM + j] = gru_update(b, SEQL - 1, j, hp);
}

// ---------------- launch ----------------
extern "C" void kernel_launch(void *const *d_in, const int *in_sizes, int n_in,
                              void *d_out, int out_size) {
    const int   *question = (const int *)d_in[0];
    const float *image    = (const float *)d_in[1];
    const float *emb      = (const float *)d_in[2];
    const float *v        = (const float *)d_in[3];
    const float *Wih      = (const float *)d_in[4];
    const float *Whh      = (const float *)d_in[5];
    const float *bih      = (const float *)d_in[6];
    const float *bhh      = (const float *)d_in[7];
    const float *Wimg2h   = (const float *)d_in[8];
    const float *bimg2h   = (const float *)d_in[9];
    const float *Wimg2h0  = (const float *)d_in[10];
    const float *bimg2h0  = (const float *)d_in[11];
    const float *Wfc1     = (const float *)d_in[12];
    const float *bfc1     = (const float *)d_in[13];
    const float *Wfc2     = (const float *)d_in[14];
    const float *bfc2     = (const float *)d_in[15];
    float *out = (float *)d_out;

    pool_kernel<<<dim3(BATCH, 8), 256>>>(image);
    build_xw_kernel<<<dim3(BATCH, SEQL), EDIM>>>(question, emb, v);
    h0_kernel<<<BATCH, HDIM>>>(Wimg2h0, bimg2h0);
    giw_gemm_kernel<<<dim3(48, 40), 256>>>(Wih, bih);
    img_gemm_kernel<<<dim3(4, 4, BATCH), 256>>>(image, Wimg2h, bimg2h);

    for (int t = 0; t < SEQL; t++) {
        step_kernel<<<BATCH, 512>>>(v, t);
        gru_gemm_kernel<<<dim3(48, 2, 4), 256>>>(Wih, Whh, bhh);
    }
    final_gates_kernel<<<BATCH, 512>>>();

    fc1_kernel<<<dim3(32, 2), 256>>>(Wfc1, bfc1);
    fc2_kernel<<<dim3(63, 2), 256>>>(Wfc2, bfc2, out);
}

// round 7
// speedup vs baseline: 2.0285x; 1.3712x over previous
#include <cuda_runtime.h>
#include <cstddef>
#include <math.h>

// Problem constants
#define BATCH 128
#define SEQL  20
#define EDIM  256
#define HDIM  512
#define NPOS  196      // 14*14
#define CDIM  2048
#define NCLS  2000
#define XDIM  768      // E + H
#define GDIM  1536     // 3*H
#define NTOT  (BATCH * NPOS)   // 25088 flattened (b,n) columns

// ---------------- scratch (static device globals; no allocation) ----------------
__device__ float d_IH[(size_t)BATCH * HDIM * NPOS];   // img_hidden, layout [b][h][n]
__device__ float d_poolp[BATCH * 8 * NPOS];           // partial channel-max
__device__ float d_hbuf[BATCH * HDIM];                // hidden state
__device__ float d_xc[BATCH * HDIM];                  // ctx * v_ctx (GRU input, ctx part)
__device__ float d_xw[BATCH * SEQL * EDIM];           // word*v for all steps
__device__ float d_giW[(size_t)BATCH * SEQL * GDIM];  // word part of GI (+bih), all steps
__device__ float d_gic0[BATCH * GDIM];                // ctx part of GI, K-half 0
__device__ float d_gic1[BATCH * GDIM];                // ctx part of GI, K-half 1
__device__ float d_gh0[BATCH * GDIM];                 // h@Whh^T half 0 (+bhh)
__device__ float d_gh1[BATCH * GDIM];                 // h@Whh^T half 1
__device__ float d_fc1[BATCH * 1024];

// ---------------- helpers ----------------
// Packed fp32 FMA: d = a*b + d on both halves (FFMA2 on sm_100+).
__device__ __forceinline__ void fma2(unsigned long long &d, unsigned long long a,
                                     unsigned long long b) {
#if defined(__CUDA_ARCH__) && (__CUDA_ARCH__ >= 1000)
    asm("fma.rn.f32x2 %0, %1, %2, %0;" : "+l"(d) : "l"(a), "l"(b));
#else
    float dx = __uint_as_float((unsigned int)(d & 0xffffffffull));
    float dy = __uint_as_float((unsigned int)(d >> 32));
    float ax = __uint_as_float((unsigned int)(a & 0xffffffffull));
    float ay = __uint_as_float((unsigned int)(a >> 32));
    float bx = __uint_as_float((unsigned int)(b & 0xffffffffull));
    float by = __uint_as_float((unsigned int)(b >> 32));
    dx = fmaf(ax, bx, dx);
    dy = fmaf(ay, by, dy);
    d = ((unsigned long long)__float_as_uint(dy) << 32) | __float_as_uint(dx);
#endif
}
// Duplicate one float into both lanes of an f32x2 (ALU pipe, overlaps FMA pipe).
__device__ __forceinline__ unsigned long long dup2(float a) {
#if defined(__CUDA_ARCH__) && (__CUDA_ARCH__ >= 1000)
    unsigned long long d;
    asm("mov.b64 %0, {%1, %1};" : "=l"(d) : "f"(a));
    return d;
#else
    unsigned int u = __float_as_uint(a);
    return ((unsigned long long)u << 32) | u;
#endif
}
__device__ __forceinline__ float2 ull2f2(unsigned long long u) {
    float2 f;
    f.x = __uint_as_float((unsigned int)(u & 0xffffffffull));
    f.y = __uint_as_float((unsigned int)(u >> 32));
    return f;
}

// ---------------- kernel 1: channel max-pool (partials over c) ----------------
__global__ void pool_kernel(const float *__restrict__ image) {
    int b = blockIdx.x, part = blockIdx.y;
    int n = threadIdx.x;
    if (n >= NPOS) return;
    const float *p = image + ((size_t)b * CDIM + (size_t)part * 256) * NPOS + n;
    float m = -3.4e38f;
#pragma unroll 8
    for (int c = 0; c < 256; c++) m = fmaxf(m, p[(size_t)c * NPOS]);
    d_poolp[((size_t)b * 8 + part) * NPOS + n] = m;
}

// ---------------- kernel 2: h0 = pooled @ W0^T + b0 ----------------
__global__ void h0_kernel(const float *__restrict__ W0, const float *__restrict__ b0) {
    __shared__ float sp[NPOS];
    int b = blockIdx.x, t = threadIdx.x;
    if (t < NPOS) {
        float m = -3.4e38f;
#pragma unroll
        for (int q = 0; q < 8; q++) m = fmaxf(m, d_poolp[((size_t)b * 8 + q) * NPOS + t]);
        sp[t] = m;
    }
    __syncthreads();
    float acc = b0[t];
    const float *wr = W0 + (size_t)t * NPOS;
#pragma unroll 4
    for (int n = 0; n < NPOS; n++) acc = fmaf(sp[n], wr[n], acc);
    d_hbuf[(size_t)b * HDIM + t] = acc;
}

// ---------------- kernel: build word inputs for all steps ----------------
__global__ void build_xw_kernel(const int *__restrict__ question,
                                const float *__restrict__ emb,
                                const float *__restrict__ v) {
    int b = blockIdx.x, t = blockIdx.y, k = threadIdx.x;
    int w = question[b * SEQL + t];
    d_xw[((size_t)b * SEQL + t) * EDIM + k] = emb[(size_t)w * EDIM + k] * v[k];
}

// ---------------- kernel: img_hidden GEMM v3 ----------------
// Flattened columns: gcol in [0, 25088) -> b = gcol/196, n = gcol%196.
// IH[b][h][n] = sum_c W[h][c] * image[b][c][n] + bias[h]
// grid (196 coltiles, 4 htiles), block 256. Tile 128h x 128col, BK=16, micro 8x8.
// A (W) and B (image) stored NON-duplicated in smem; A dup'd into f32x2 via mov.b64.
#define IMG_LDA 132   // padded row stride (floats), 16B-aligned rows
__global__ void __launch_bounds__(256)
img_gemm_kernel(const float *__restrict__ image,
                const float *__restrict__ W,
                const float *__restrict__ bias) {
    __shared__ __align__(16) float As[16 * IMG_LDA];  // [k][h], 128 used per row
    __shared__ __align__(16) float Bs[16 * IMG_LDA];  // [k][col], 128 used per row
    const int t = threadIdx.x;
    const int n0 = blockIdx.x * 128, h0 = blockIdx.y * 128;
    const int tx = t & 15, ty = t >> 4;            // tx: col (x8), ty: h (x8)

    unsigned long long acc[8][4];
#pragma unroll
    for (int r = 0; r < 8; r++)
#pragma unroll
        for (int p = 0; p < 4; p++) acc[r][p] = 0ull;

    // A loader: 128 rows x 16k, 2 float4 per thread
    const int ar = t >> 1, ac = (t & 1) * 8;
    // B loader: 16 k-rows x 128 cols, 2 float4 per thread
    const int br = t >> 4, bj = (t & 15) * 8;
    // precompute (b, n) for the two B float4s (each fully inside one b: cols mult of 4)
    const int gc0 = n0 + bj, gc1 = gc0 + 4;
    const float *bp0 = image + ((size_t)(gc0 / NPOS) * CDIM) * NPOS + (gc0 % NPOS);
    const float *bp1 = image + ((size_t)(gc1 / NPOS) * CDIM) * NPOS + (gc1 % NPOS);
    const float *apw = W + (size_t)(h0 + ar) * CDIM + ac;

    for (int k0 = 0; k0 < CDIM; k0 += 16) {
        float4 a4 = *(const float4 *)(apw + k0);
        float4 a5 = *(const float4 *)(apw + k0 + 4);
        As[(ac + 0) * IMG_LDA + ar] = a4.x;
        As[(ac + 1) * IMG_LDA + ar] = a4.y;
        As[(ac + 2) * IMG_LDA + ar] = a4.z;
        As[(ac + 3) * IMG_LDA + ar] = a4.w;
        As[(ac + 4) * IMG_LDA + ar] = a5.x;
        As[(ac + 5) * IMG_LDA + ar] = a5.y;
        As[(ac + 6) * IMG_LDA + ar] = a5.z;
        As[(ac + 7) * IMG_LDA + ar] = a5.w;
        size_t rowoff = (size_t)(k0 + br) * NPOS;
        *(float4 *)&Bs[br * IMG_LDA + bj]     = *(const float4 *)(bp0 + rowoff);
        *(float4 *)&Bs[br * IMG_LDA + bj + 4] = *(const float4 *)(bp1 + rowoff);
        __syncthreads();
#pragma unroll
        for (int kk = 0; kk < 16; kk++) {
            float4 af0 = *(const float4 *)&As[kk * IMG_LDA + ty * 8];
            float4 af1 = *(const float4 *)&As[kk * IMG_LDA + ty * 8 + 4];
            unsigned long long ad[8];
            ad[0] = dup2(af0.x); ad[1] = dup2(af0.y); ad[2] = dup2(af0.z); ad[3] = dup2(af0.w);
            ad[4] = dup2(af1.x); ad[5] = dup2(af1.y); ad[6] = dup2(af1.z); ad[7] = dup2(af1.w);
            ulonglong2 b0 = *(const ulonglong2 *)&Bs[kk * IMG_LDA + tx * 8];
            ulonglong2 b1 = *(const ulonglong2 *)&Bs[kk * IMG_LDA + tx * 8 + 4];
#pragma unroll
            for (int r = 0; r < 8; r++) {
                fma2(acc[r][0], ad[r], b0.x);
                fma2(acc[r][1], ad[r], b0.y);
                fma2(acc[r][2], ad[r], b1.x);
                fma2(acc[r][3], ad[r], b1.y);
            }
        }
        __syncthreads();
    }
    // epilogue: pairs never cross a b-boundary (gcol even, 196 even)
#pragma unroll
    for (int p = 0; p < 4; p++) {
        int gcol = n0 + tx * 8 + 2 * p;
        int bb = gcol / NPOS, nn = gcol % NPOS;
        float *dstb = d_IH + ((size_t)bb * HDIM) * NPOS + nn;
#pragma unroll
        for (int r = 0; r < 8; r++) {
            int h = h0 + ty * 8 + r;
            float2 v2 = ull2f2(acc[r][p]);
            float bi = bias[h];
            dstb[(size_t)h * NPOS]     = v2.x + bi;
            dstb[(size_t)h * NPOS + 1] = v2.y + bi;
        }
    }
}

// ---------------- generic NT GEMM with K-offsets (non-dup A + reg pack) ----------------
// C[m][j] = sum_{k<Klen} A[m][koffA+k]*W[j][koffW+k] (+ bias[j])
// Tile 64m x 64n, BK=16, block 256 (16x16), micro 4x4. Klen % 16 == 0, M exact.
#define G_LDS 68   // padded row stride (floats), 16B-aligned rows
__device__ __forceinline__ void gemm_nt_dev(const float *__restrict__ A, int lda, int koffA,
                                            const float *__restrict__ W, int ldw, int koffW,
                                            const float *__restrict__ bias,
                                            int N, int Klen,
                                            float *__restrict__ C, int ldc, bool relu) {
    __shared__ __align__(16) float As[16 * G_LDS];  // [k][m]
    __shared__ __align__(16) float Bs[16 * G_LDS];  // [k][n]
    const int t = threadIdx.x;
    const int m0 = blockIdx.y * 64, j0 = blockIdx.x * 64;
    const int tx = t & 15, ty = t >> 4;
    unsigned long long acc[4][2];
#pragma unroll
    for (int r = 0; r < 4; r++) { acc[r][0] = 0ull; acc[r][1] = 0ull; }
    const int lr = t >> 2, lc = (t & 3) * 4;  // loader: 64 rows x 4 float4

    for (int k0 = 0; k0 < Klen; k0 += 16) {
        float4 a4 = *(const float4 *)(A + (size_t)(m0 + lr) * lda + koffA + k0 + lc);
        As[(lc + 0) * G_LDS + lr] = a4.x;
        As[(lc + 1) * G_LDS + lr] = a4.y;
        As[(lc + 2) * G_LDS + lr] = a4.z;
        As[(lc + 3) * G_LDS + lr] = a4.w;
        float4 b4 = make_float4(0.f, 0.f, 0.f, 0.f);
        if (j0 + lr < N) b4 = *(const float4 *)(W + (size_t)(j0 + lr) * ldw + koffW + k0 + lc);
        Bs[(lc + 0) * G_LDS + lr] = b4.x;
        Bs[(lc + 1) * G_LDS + lr] = b4.y;
        Bs[(lc + 2) * G_LDS + lr] = b4.z;
        Bs[(lc + 3) * G_LDS + lr] = b4.w;
        __syncthreads();
#pragma unroll
        for (int kk = 0; kk < 16; kk++) {
            float4 af = *(const float4 *)&As[kk * G_LDS + ty * 4];
            unsigned long long a0 = dup2(af.x), a1 = dup2(af.y),
                               a2 = dup2(af.z), a3 = dup2(af.w);
            ulonglong2 bv = *(const ulonglong2 *)&Bs[kk * G_LDS + tx * 4];
            fma2(acc[0][0], a0, bv.x); fma2(acc[0][1], a0, bv.y);
            fma2(acc[1][0], a1, bv.x); fma2(acc[1][1], a1, bv.y);
            fma2(acc[2][0], a2, bv.x); fma2(acc[2][1], a2, bv.y);
            fma2(acc[3][0], a3, bv.x); fma2(acc[3][1], a3, bv.y);
        }
        __syncthreads();
    }
#pragma unroll
    for (int r = 0; r < 4; r++) {
        int m = m0 + ty * 4 + r;
#pragma unroll
        for (int p = 0; p < 2; p++) {
            float2 v2 = ull2f2(acc[r][p]);
            int n = j0 + tx * 4 + p * 2;
            if (n < N) {
                float o = v2.x + (bias ? bias[n] : 0.f);
                if (relu) o = fmaxf(o, 0.f);
                C[(size_t)m * ldc + n] = o;
            }
            if (n + 1 < N) {
                float o = v2.y + (bias ? bias[n + 1] : 0.f);
                if (relu) o = fmaxf(o, 0.f);
                C[(size_t)m * ldc + n + 1] = o;
            }
        }
    }
}

// giW = xw @ Wih[:, 0:256]^T + bih  over all (b,t): M=2560. grid (24, 40)
__global__ void __launch_bounds__(256)
giw_gemm_kernel(const float *__restrict__ Wih, const float *__restrict__ bih) {
    gemm_nt_dev(d_xw, EDIM, 0, Wih, XDIM, 0, bih, GDIM, EDIM, d_giW, GDIM, false);
}

// Per-step GRU GEMMs, split-K(=2). grid (24, 2, 4)
__global__ void __launch_bounds__(256)
gru_gemm_kernel(const float *__restrict__ Wih, const float *__restrict__ Whh,
                const float *__restrict__ bhh) {
    int z = blockIdx.z;
    if (z == 0)
        gemm_nt_dev(d_xc, HDIM, 0,   Wih, XDIM, EDIM,       0,   GDIM, 256, d_gic0, GDIM, false);
    else if (z == 1)
        gemm_nt_dev(d_xc, HDIM, 256, Wih, XDIM, EDIM + 256, 0,   GDIM, 256, d_gic1, GDIM, false);
    else if (z == 2)
        gemm_nt_dev(d_hbuf, HDIM, 0,   Whh, HDIM, 0,   bhh, GDIM, 256, d_gh0, GDIM, false);
    else
        gemm_nt_dev(d_hbuf, HDIM, 256, Whh, HDIM, 256, 0,   GDIM, 256, d_gh1, GDIM, false);
}

__global__ void __launch_bounds__(256)
fc1_kernel(const float *__restrict__ W, const float *__restrict__ b) {
    gemm_nt_dev(d_hbuf, HDIM, 0, W, HDIM, 0, b, 1024, HDIM, d_fc1, 1024, true);
}
__global__ void __launch_bounds__(256)
fc2_kernel(const float *__restrict__ W, const float *__restrict__ b,
           float *__restrict__ out) {
    gemm_nt_dev(d_fc1, 1024, 0, W, 1024, 0, b, NCLS, 1024, out, NCLS, false);
}

// ---------------- gate math ----------------
__device__ __forceinline__ float gru_update(int b, int tprev, int j, float hp) {
    size_t mw = ((size_t)b * SEQL + tprev) * GDIM;
    size_t mc = (size_t)b * GDIM;
    float gir = d_giW[mw + j]            + d_gic0[mc + j]            + d_gic1[mc + j];
    float giz = d_giW[mw + HDIM + j]     + d_gic0[mc + HDIM + j]     + d_gic1[mc + HDIM + j];
    float gin = d_giW[mw + 2 * HDIM + j] + d_gic0[mc + 2 * HDIM + j] + d_gic1[mc + 2 * HDIM + j];
    float ghr = d_gh0[mc + j]            + d_gh1[mc + j];
    float ghz = d_gh0[mc + HDIM + j]     + d_gh1[mc + HDIM + j];
    float ghn = d_gh0[mc + 2 * HDIM + j] + d_gh1[mc + 2 * HDIM + j];
    float r = 1.f / (1.f + expf(-(gir + ghr)));
    float z = 1.f / (1.f + expf(-(giz + ghz)));
    float n = tanhf(gin + r * ghn);
    return (1.f - z) * n + z * hp;
}

// ---------------- per-step fused kernel ----------------
__global__ void __launch_bounds__(512)
step_kernel(const float *__restrict__ v, int t) {
    __shared__ float sh_h[HDIM];
    __shared__ float sh_p[2 * NPOS];
    __shared__ float sh_e[NPOS];
    __shared__ float sh_red[8];
    __shared__ float sh_scalar[2];
    const int b = blockIdx.x, tid = threadIdx.x;

    // phase 0: gates
    {
        float hp = d_hbuf[(size_t)b * HDIM + tid];
        float hn = (t == 0) ? hp : gru_update(b, t - 1, tid, hp);
        sh_h[tid] = hn;
        if (t != 0) d_hbuf[(size_t)b * HDIM + tid] = hn;
    }
    __syncthreads();

    // phase 1: energy, h split in two halves of 256
    {
        int half = (tid >= 256) ? 1 : 0;
        int n = tid - half * 256;
        if (n < NPOS) {
            const float *col = d_IH + ((size_t)b * HDIM + half * 256) * NPOS + n;
            const float *hh = sh_h + half * 256;
            float a0 = 0.f, a1 = 0.f, a2 = 0.f, a3 = 0.f;
#pragma unroll 8
            for (int h = 0; h < 256; h += 4) {
                a0 = fmaf(hh[h + 0], col[(size_t)(h + 0) * NPOS], a0);
                a1 = fmaf(hh[h + 1], col[(size_t)(h + 1) * NPOS], a1);
                a2 = fmaf(hh[h + 2], col[(size_t)(h + 2) * NPOS], a2);
                a3 = fmaf(hh[h + 3], col[(size_t)(h + 3) * NPOS], a3);
            }
            sh_p[half * NPOS + n] = (a0 + a1) + (a2 + a3);
        }
    }
    __syncthreads();

    // softmax over 196
    float e = -3.4e38f;
    if (tid < NPOS) e = sh_p[tid] + sh_p[NPOS + tid];
    if (tid < 224) {
        float m = e;
#pragma unroll
        for (int o = 16; o > 0; o >>= 1) m = fmaxf(m, __shfl_xor_sync(0xffffffffu, m, o));
        if ((tid & 31) == 0) sh_red[tid >> 5] = m;
    }
    __syncthreads();
    if (tid == 0) {
        float mm = sh_red[0];
#pragma unroll
        for (int i = 1; i < 7; i++) mm = fmaxf(mm, sh_red[i]);
        sh_scalar[0] = mm;
    }
    __syncthreads();
    float mx = sh_scalar[0];
    float ex = (tid < NPOS) ? expf(e - mx) : 0.f;
    if (tid < NPOS) sh_e[tid] = ex;
    if (tid < 224) {
        float s = ex;
#pragma unroll
        for (int o = 16; o > 0; o >>= 1) s += __shfl_xor_sync(0xffffffffu, s, o);
        if ((tid & 31) == 0) sh_red[tid >> 5] = s;
    }
    __syncthreads();
    if (tid == 0) {
        float ss = 0.f;
#pragma unroll
        for (int i = 0; i < 7; i++) ss += sh_red[i];
        sh_scalar[1] = 1.f / ss;
    }
    __syncthreads();
    float inv = sh_scalar[1];

    // phase 2: context; 16 warps x 32 h-rows each
    {
        int w = tid >> 5, lane = tid & 31;
        int hbase = w * 32;
#pragma unroll 4
        for (int rr = 0; rr < 32; rr++) {
            int h = hbase + rr;
            const float *row = d_IH + ((size_t)b * HDIM + h) * NPOS;
            float acc = 0.f;
#pragma unroll
            for (int c = 0; c < 7; c++) {
                int n = c * 32 + lane;
                if (n < NPOS) acc = fmaf(sh_e[n], row[n], acc);
            }
#pragma unroll
            for (int o = 16; o > 0; o >>= 1) acc += __shfl_xor_sync(0xffffffffu, acc, o);
            if (lane == 0)
                d_xc[(size_t)b * HDIM + h] = acc * inv * v[EDIM + h];
        }
    }
}

// ---------------- final gate update after last GEMM ----------------
__global__ void __launch_bounds__(512) final_gates_kernel() {
    int b = blockIdx.x, j = threadIdx.x;
    float hp = d_hbuf[(size_t)b * HDIM + j];
    d_hbuf[(size_t)b * HDIM + j] = gru_update(b, SEQL - 1, j, hp);
}

// ---------------- launch ----------------
extern "C" void kernel_launch(void *const *d_in, const int *in_sizes, int n_in,
                              void *d_out, int out_size) {
    const int   *question = (const int *)d_in[0];
    const float *image    = (const float *)d_in[1];
    const float *emb      = (const float *)d_in[2];
    const float *v        = (const float *)d_in[3];
    const float *Wih      = (const float *)d_in[4];
    const float *Whh      = (const float *)d_in[5];
    const float *bih      = (const float *)d_in[6];
    const float *bhh      = (const float *)d_in[7];
    const float *Wimg2h   = (const float *)d_in[8];
    const float *bimg2h   = (const float *)d_in[9];
    const float *Wimg2h0  = (const float *)d_in[10];
    const float *bimg2h0  = (const float *)d_in[11];
    const float *Wfc1     = (const float *)d_in[12];
    const float *bfc1     = (const float *)d_in[13];
    const float *Wfc2     = (const float *)d_in[14];
    const float *bfc2     = (const float *)d_in[15];
    float *out = (float *)d_out;

    pool_kernel<<<dim3(BATCH, 8), 256>>>(image);
    build_xw_kernel<<<dim3(BATCH, SEQL), EDIM>>>(question, emb, v);
    h0_kernel<<<BATCH, HDIM>>>(Wimg2h0, bimg2h0);
    giw_gemm_kernel<<<dim3(24, 40), 256>>>(Wih, bih);
    img_gemm_kernel<<<dim3(196, 4), 256>>>(image, Wimg2h, bimg2h);

    for (int t = 0; t < SEQL; t++) {
        step_kernel<<<BATCH, 512>>>(v, t);
        gru_gemm_kernel<<<dim3(24, 2, 4), 256>>>(Wih, Whh, bhh);
    }
    final_gates_kernel<<<BATCH, 512>>>();

    fc1_kernel<<<dim3(16, 2), 256>>>(Wfc1, bfc1);
    fc2_kernel<<<dim3(32, 2), 256>>>(Wfc2, bfc2, out);
}